// round 3
// baseline (speedup 1.0000x reference)
#include <cuda_runtime.h>
#include <cstdint>
#include <cstddef>

// Problem constants (fixed shapes from reference):
//   x: [2048, 4096] f32, weights: [32, 16] f32, biases: [16] f32
//   out: [2048, 4096*16] f32
//   out[t, n*16+f] = relu(bias[f] + sum_{j=0..31} x[t-2j-1, n] * w_pn[j][f])
//   (terms with t-2j-1 < 0 are zero; w_pn = l2-normalized relu(weights) per filter)

#define T_DIM 2048
#define N_DIM 4096
#define L_DIM 32
#define F_DIM 16
#define OUTW  (N_DIM * F_DIM)   // 65536 floats per output row

using ull = unsigned long long;

// --- packed f32x2 helpers (sm_103a FFMA2 path) ---------------------------

__device__ __forceinline__ ull dup2(float v) {
    ull r;
    unsigned u = __float_as_uint(v);
    asm("mov.b64 %0, {%1, %1};" : "=l"(r) : "r"(u));
    return r;
}

__device__ __forceinline__ void fma2(ull& d, ull a, ull b) {
    // d = a * b + d  (two fp32 FMAs in one FFMA2)
    asm("fma.rn.f32x2 %0, %1, %2, %0;" : "+l"(d) : "l"(a), "l"(b));
}

__device__ __forceinline__ float2 unpack2(ull v) {
    float2 r;
    asm("mov.b64 {%0, %1}, %2;" : "=f"(r.x), "=f"(r.y) : "l"(v));
    return r;
}

// --- x column load with optional low-side clamp --------------------------

template<bool GUARD>
__device__ __forceinline__ float ldx(const float* __restrict__ xn, int r) {
    if (GUARD) {
        return (r >= 0) ? __ldg(xn + (size_t)r * N_DIM) : 0.0f;
    }
    return __ldg(xn + (size_t)r * N_DIM);
}

// --- main per-warp-lane tile: one n column, 4 consecutive t, all 16 f ----

template<bool GUARD>
__device__ __forceinline__ void compute_tile(
    const float* __restrict__ xn,     // x + n  (column base)
    float* __restrict__ outp,         // out + n*16
    const ull* __restrict__ sw8,      // smem weights as float2 pairs [32][8]
    const ull* __restrict__ sb2,      // smem biases as float2 pairs [8]
    int t0)
{
    // acc[tt][p] holds {out[t0+tt, 2p], out[t0+tt, 2p+1]} pre-relu
    ull acc[4][8];
#pragma unroll
    for (int p = 0; p < 8; ++p) {
        ull b = sb2[p];
        acc[0][p] = b; acc[1][p] = b; acc[2][p] = b; acc[3][p] = b;
    }

    // Register sliding window over x rows. At iteration j we need rows
    //   t0 - 2j - 1 + i   for i = 0..3  (i.e. x[(t0+i) - 2j - 1])
    // Window shifts DOWN by 2 rows per j.
    float w0 = ldx<GUARD>(xn, t0 - 1);
    float w1 = ldx<GUARD>(xn, t0);
    float w2 = ldx<GUARD>(xn, t0 + 1);
    float w3 = ldx<GUARD>(xn, t0 + 2);

#pragma unroll
    for (int j = 0; j < L_DIM; ++j) {
        ull x0 = dup2(w0);
        ull x1 = dup2(w1);
        ull x2 = dup2(w2);
        ull x3 = dup2(w3);
#pragma unroll
        for (int p = 0; p < 8; ++p) {
            ull wj = sw8[j * 8 + p];     // broadcast LDS.64, reused 4x
            fma2(acc[0][p], x0, wj);
            fma2(acc[1][p], x1, wj);
            fma2(acc[2][p], x2, wj);
            fma2(acc[3][p], x3, wj);
        }
        if (j < L_DIM - 1) {
            // next base row = t0 - 2(j+1) - 1 = t0 - 2j - 3
            w3 = w1;
            w2 = w0;
            w0 = ldx<GUARD>(xn, t0 - 2 * j - 3);
            w1 = ldx<GUARD>(xn, t0 - 2 * j - 2);
        }
    }

    // relu + store: 16 contiguous floats per t -> 4x STG.128.
    // Warp lanes are consecutive n -> warp writes a contiguous 2KB block.
#pragma unroll
    for (int tt = 0; tt < 4; ++tt) {
        float4* dst = reinterpret_cast<float4*>(outp + (size_t)(t0 + tt) * OUTW);
#pragma unroll
        for (int q = 0; q < 4; ++q) {
            float2 a = unpack2(acc[tt][2 * q]);
            float2 b = unpack2(acc[tt][2 * q + 1]);
            float4 v;
            v.x = fmaxf(a.x, 0.0f);
            v.y = fmaxf(a.y, 0.0f);
            v.z = fmaxf(b.x, 0.0f);
            v.w = fmaxf(b.y, 0.0f);
            dst[q] = v;
        }
    }
}

__global__ void __launch_bounds__(128)
tlayer_kernel(const float* __restrict__ x,
              const float* __restrict__ W,
              const float* __restrict__ B,
              float* __restrict__ out)
{
    __shared__ __align__(8) float sw[L_DIM * F_DIM];  // normalized weights [j][f]
    __shared__ __align__(8) float sb[F_DIM];

    const int tid = threadIdx.x;

    // Per-block weight prep: relu, per-filter l2-normalize (matches reference).
    // 16 threads, 2x32 tiny loops -- negligible vs. the main loop.
    if (tid < F_DIM) {
        float ss = 0.0f;
        for (int j = 0; j < L_DIM; ++j) {
            float wv = fmaxf(__ldg(W + j * F_DIM + tid), 0.0f);
            ss += wv * wv;
        }
        float inv = rsqrtf(fmaxf(ss, 1e-12f));
        for (int j = 0; j < L_DIM; ++j) {
            sw[j * F_DIM + tid] = fmaxf(__ldg(W + j * F_DIM + tid), 0.0f) * inv;
        }
        sb[tid] = __ldg(B + tid);
    }
    __syncthreads();

    const int lane = tid & 31;
    const int warp = tid >> 5;

    const int n  = blockIdx.x * 32 + lane;         // 128 n-blocks
    const int t0 = blockIdx.y * 16 + warp * 4;     // 128 t-blocks, 4 warps x 4 t

    const float* xn   = x + n;
    float*       outp = out + (size_t)n * F_DIM;
    const ull*   sw8  = reinterpret_cast<const ull*>(sw);
    const ull*   sb2  = reinterpret_cast<const ull*>(sb);

    // Rows accessed reach down to t0 - 63; guard only near the start.
    if (t0 >= 63) {
        compute_tile<false>(xn, outp, sw8, sb2, t0);
    } else {
        compute_tile<true>(xn, outp, sw8, sb2, t0);
    }
}

extern "C" void kernel_launch(void* const* d_in, const int* in_sizes, int n_in,
                              void* d_out, int out_size) {
    (void)in_sizes; (void)n_in; (void)out_size;
    const float* x = (const float*)d_in[0];   // [2048, 4096]
    const float* W = (const float*)d_in[1];   // [32, 16]
    const float* B = (const float*)d_in[2];   // [16]
    float* out = (float*)d_out;               // [2048, 65536]

    dim3 grid(N_DIM / 32, T_DIM / 16);        // (128, 128)
    tlayer_kernel<<<grid, 128>>>(x, W, B, out);
}